// round 1
// baseline (speedup 1.0000x reference)
#include <cuda_runtime.h>
#include <math.h>

// Problem constants
#define Bn 8
#define Ln 8192
#define Wn 128
#define MODESn 32
#define NLn 4
#define SEGn 4
#define CMn 8
#define LSn 2048   // Ln / SEGn
#define J2 64      // 2*MODES (cos rows then sin rows)
#define KSPLIT 32

// ---------------- device scratch (no allocations allowed) ----------------
__device__ float g_h[Bn*Wn*Ln];        // 32 MB  current h, [b][c][l]
__device__ float g_fno[Bn*Wn*Ln];      // 32 MB  x_fno / fc1 output
__device__ float g_basis[J2*Ln];       // 2 MB   basis[j][l]: j<32 cos, j>=32 sin
__device__ float g_part[KSPLIT*Bn*Wn*J2]; // 8 MB DFT split-K partials
__device__ float g_hf2[Bn*Wn*J2];      // DFT results per row: [r][j]
__device__ float g_spec[Bn*J2*Wn];     // spectral coeffs [b][j][o]
__device__ float g_rec[Bn*Wn*SEGn];    // tanh-recovered CFT values
__device__ float g_g2v[Bn*Wn*SEGn];    // precomputed gate contribution of x_cft
__device__ float g_wbar[NLn*SEGn*CMn*Wn];
__device__ float g_mn[SEGn];
__device__ float g_mx[SEGn];

__device__ __forceinline__ float gelu_exact(float v) {
    return 0.5f * v * (1.0f + erff(v * 0.70710678118654752f));
}

__device__ __forceinline__ void atomicMinF(float* addr, float v) {
    int* ia = (int*)addr;
    int old = *ia;
    while (__int_as_float(old) > v) {
        int assumed = old;
        old = atomicCAS(ia, assumed, __float_as_int(v));
        if (old == assumed) break;
    }
}
__device__ __forceinline__ void atomicMaxF(float* addr, float v) {
    int* ia = (int*)addr;
    int old = *ia;
    while (__int_as_float(old) < v) {
        int assumed = old;
        old = atomicCAS(ia, assumed, __float_as_int(v));
        if (old == assumed) break;
    }
}

// ---------------- basis table: cos/sin(2*pi*k*l/L) ----------------
__global__ void k_basis() {
    int t = blockIdx.x * blockDim.x + threadIdx.x;   // MODES*L threads
    int k = t / Ln, l = t % Ln;
    // k*l < 2^24 so exact in float; x = 2*k*l/L measured in units of pi
    float x = (float)(k * l) * (1.0f / 4096.0f);
    float s, c;
    sincospif(x, &s, &c);
    g_basis[k * Ln + l] = c;
    g_basis[(MODESn + k) * Ln + l] = s;
}

// wbar[i,s,m,c] = mean_o cheb_w[i,s,m,c,o]
__global__ void k_wbar(const float* __restrict__ cheb_w) {
    int ism = blockIdx.x;        // NL*SEG*CM = 128
    int c = threadIdx.x;         // 128
    const float* p = cheb_w + ((long)ism * Wn + c) * Wn;
    float s = 0.f;
    for (int o = 0; o < Wn; o++) s += p[o];
    g_wbar[ism * Wn + c] = s * (1.0f / Wn);
}

// fc0: h[b][c][l] = x[b][l][0]*w[0][c] + x[b][l][1]*w[1][c] + bias[c]
__global__ void k_fc0(const float* __restrict__ x, const float* __restrict__ w,
                      const float* __restrict__ bias) {
    long t = (long)blockIdx.x * 256 + threadIdx.x;   // B*W*L
    int l = (int)(t % Ln);
    long bc = t / Ln;
    int c = (int)(bc % Wn);
    int b = (int)(bc / Wn);
    long xb = ((long)b * Ln + l) * 2;
    g_h[t] = x[xb] * w[c] + x[xb + 1] * w[Wn + c] + bias[c];
}

__global__ void k_init_mnmx() {
    int t = threadIdx.x;
    if (t < SEGn) { g_mn[t] = INFINITY; g_mx[t] = -INFINITY; }
}

// per-segment global min/max over h (each block covers one (b,c,s) chunk of 2048)
__global__ void k_minmax() {
    int blk = blockIdx.x;               // B*W*SEG = 4096
    int s = blk & 3;
    long base = (long)blk * LSn;
    float mn = INFINITY, mx = -INFINITY;
#pragma unroll
    for (int it = 0; it < LSn / 256; it++) {
        float v = g_h[base + it * 256 + threadIdx.x];
        mn = fminf(mn, v); mx = fmaxf(mx, v);
    }
#pragma unroll
    for (int o = 16; o; o >>= 1) {
        mn = fminf(mn, __shfl_xor_sync(0xffffffffu, mn, o));
        mx = fmaxf(mx, __shfl_xor_sync(0xffffffffu, mx, o));
    }
    __shared__ float smn[8], smx[8];
    if ((threadIdx.x & 31) == 0) { smn[threadIdx.x >> 5] = mn; smx[threadIdx.x >> 5] = mx; }
    __syncthreads();
    if (threadIdx.x == 0) {
        for (int w = 1; w < 8; w++) { mn = fminf(mn, smn[w]); mx = fmaxf(mx, smx[w]); }
        atomicMinF(&g_mn[s], mn);
        atomicMaxF(&g_mx[s], mx);
    }
}

// Chebyshev coefficients + filtering + tanh -> rec[b,c,s]
__global__ void k_cheb(int layer) {
    __shared__ float sred[8][CMn];
    __shared__ float sC[CMn];
    int blk = blockIdx.x;           // (b*W+c)*SEG + s
    int s = blk & 3;
    int bc = blk >> 2;
    int c = bc & (Wn - 1);
    int tid = threadIdx.x;
    long base = (long)bc * Ln + s * LSn;
    float mn = g_mn[s], mx = g_mx[s];
    float sc = 2.0f / (mx - mn);
    float a[CMn];
#pragma unroll
    for (int m = 0; m < CMn; m++) a[m] = 0.f;
#pragma unroll
    for (int it = 0; it < LSn / 256; it++) {
        float v = g_h[base + it * 256 + tid];
        float xn = (v - mn) * sc - 1.0f;
        float Tpp = 1.0f, Tp = xn;
        a[0] += xn;        // xn * T0
        a[1] += xn * xn;   // xn * T1
#pragma unroll
        for (int m = 2; m < CMn; m++) {
            float Tn = 2.0f * xn * Tp - Tpp;
            a[m] += xn * Tn;
            Tpp = Tp; Tp = Tn;
        }
    }
#pragma unroll
    for (int m = 0; m < CMn; m++)
#pragma unroll
        for (int o = 16; o; o >>= 1) a[m] += __shfl_xor_sync(0xffffffffu, a[m], o);
    if ((tid & 31) == 0)
#pragma unroll
        for (int m = 0; m < CMn; m++) sred[tid >> 5][m] = a[m];
    __syncthreads();
    if (tid < CMn) {
        float t = 0.f;
        for (int w = 0; w < 8; w++) t += sred[w][tid];
        sC[tid] = t * (1.0f / LSn);
    }
    __syncthreads();
    if (tid == 0) {
        float r = 0.f;
#pragma unroll
        for (int m = 0; m < CMn; m++)
            r += sC[m] * g_wbar[((layer * SEGn + s) * CMn + m) * Wn + c];
        g_rec[blk] = tanhf(r);
    }
}

// DFT: hf2[r][j] = sum_l h[r][l] * basis[j][l] ; split-K partials
__global__ void __launch_bounds__(256) k_dft() {
    __shared__ float As[16][64];
    __shared__ float Bs[16][64];
    int tid = threadIdx.x;
    int tr = tid & 15, tj = tid >> 4;
    int r0 = blockIdx.x * 64;          // 16 row tiles
    int l0 = blockIdx.y * (Ln / KSPLIT); // 32 k-splits, 256 each
    int ldr = tid >> 2, ldq = tid & 3;
    float acc[4][4];
#pragma unroll
    for (int i = 0; i < 4; i++)
#pragma unroll
        for (int j = 0; j < 4; j++) acc[i][j] = 0.f;

    for (int lc = 0; lc < Ln / KSPLIT; lc += 16) {
        float4 av = *(const float4*)&g_h[(long)(r0 + ldr) * Ln + l0 + lc + ldq * 4];
        As[ldq * 4 + 0][ldr] = av.x; As[ldq * 4 + 1][ldr] = av.y;
        As[ldq * 4 + 2][ldr] = av.z; As[ldq * 4 + 3][ldr] = av.w;
        float4 bv = *(const float4*)&g_basis[(long)ldr * Ln + l0 + lc + ldq * 4];
        Bs[ldq * 4 + 0][ldr] = bv.x; Bs[ldq * 4 + 1][ldr] = bv.y;
        Bs[ldq * 4 + 2][ldr] = bv.z; Bs[ldq * 4 + 3][ldr] = bv.w;
        __syncthreads();
#pragma unroll
        for (int ll = 0; ll < 16; ll++) {
            float4 a4 = *(const float4*)&As[ll][tr * 4];
            float4 b4 = *(const float4*)&Bs[ll][tj * 4];
            float ar[4] = {a4.x, a4.y, a4.z, a4.w};
            float br[4] = {b4.x, b4.y, b4.z, b4.w};
#pragma unroll
            for (int i = 0; i < 4; i++)
#pragma unroll
                for (int j = 0; j < 4; j++)
                    acc[i][j] = fmaf(ar[i], br[j], acc[i][j]);
        }
        __syncthreads();
    }
#pragma unroll
    for (int i = 0; i < 4; i++) {
        long ob = (long)blockIdx.y * (Bn * Wn * J2) + (long)(r0 + tr * 4 + i) * J2 + tj * 4;
        *(float4*)&g_part[ob] = make_float4(acc[i][0], acc[i][1], acc[i][2], acc[i][3]);
    }
}

__global__ void k_dft_reduce() {
    int t = blockIdx.x * 256 + threadIdx.x;  // B*W*J2 = 65536
    float s = 0.f;
#pragma unroll
    for (int q = 0; q < KSPLIT; q++) s += g_part[(long)q * (Bn * Wn * J2) + t];
    g_hf2[t] = s;
}

// mode mixing + scale folding: spec[b][j][o]
__global__ void k_modemix(const float* __restrict__ wr, const float* __restrict__ wi,
                          int layer) {
    int b = blockIdx.y;
    int o = blockIdx.x * 8 + (threadIdx.x >> 5);
    int k = threadIdx.x & 31;
    const float* wrp = wr + (long)layer * Wn * Wn * MODESn;
    const float* wip = wi + (long)layer * Wn * Wn * MODESn;
    float omr = 0.f, omi = 0.f;
    for (int i = 0; i < Wn; i++) {
        float fr = g_hf2[(b * Wn + i) * J2 + k];          // sum h*cos  (= Re)
        float fs = g_hf2[(b * Wn + i) * J2 + 32 + k];     // sum h*sin  (Im = -fs)
        long wix = ((long)i * Wn + o) * MODESn + k;
        float a = wrp[wix], bb = wip[wix];
        omr += fr * a + fs * bb;   // Re*wr - Im*wi
        omi += fr * bb - fs * a;   // Re*wi + Im*wr
    }
    float scale = ((k == 0) ? 1.0f : 2.0f) * (1.0f / Ln);
    g_spec[(b * J2 + k) * Wn + o] = scale * omr;
    g_spec[(b * J2 + 32 + k) * Wn + o] = -scale * omi;
}

// g2[b][o][s] = sum_c rec[b][c][s] * gate_w[layer][W+c][o]
__global__ void k_g2(const float* __restrict__ gate_w, int layer) {
    int s = blockIdx.x, b = blockIdx.y, o = threadIdx.x;
    const float* gw = gate_w + (long)layer * 2 * Wn * Wn + Wn * Wn;
    float acc = 0.f;
    for (int c = 0; c < Wn; c++)
        acc += g_rec[(b * Wn + c) * SEGn + s] * gw[c * Wn + o];
    g_g2v[(b * Wn + o) * SEGn + s] = acc;
}

__device__ __forceinline__ void gemm_tile_compute(const float (&Ws)[16][128],
                                                  const float (&Is)[16][128],
                                                  int tx, int ty, float (&acc)[8][8]) {
#pragma unroll
    for (int cc = 0; cc < 16; cc++) {
        float wv[8], iv[8];
        *(float4*)&wv[0] = *(const float4*)&Ws[cc][tx * 8];
        *(float4*)&wv[4] = *(const float4*)&Ws[cc][tx * 8 + 4];
        *(float4*)&iv[0] = *(const float4*)&Is[cc][ty * 8];
        *(float4*)&iv[4] = *(const float4*)&Is[cc][ty * 8 + 4];
#pragma unroll
        for (int i = 0; i < 8; i++)
#pragma unroll
            for (int j = 0; j < 8; j++)
                acc[i][j] = fmaf(wv[i], iv[j], acc[i][j]);
    }
}

// Channel-mix GEMM: out[b,o,l] = act( sum_c Wt[c][o] * in[b,c,l] + ... )
// MODE 0: conv + spectral extension + gelu -> g_fno
// MODE 1: gate (sigmoid) + residual update -> g_h
// MODE 2: fc1 + gelu -> g_fno
template<int MODE>
__global__ void __launch_bounds__(256, 2) k_gemm(const float* __restrict__ Wt,
                                                 const float* __restrict__ bias) {
    __shared__ float Ws[16][128];
    __shared__ float Is[16][128];
    const int b = blockIdx.y;
    const int l0 = blockIdx.x * 128;
    const int tid = threadIdx.x;
    const int tx = tid & 15;     // output-channel group
    const int ty = tid >> 4;     // position group (also loader row)
    const float* inbase = (MODE == 1) ? g_fno : g_h;

    float acc[8][8];
#pragma unroll
    for (int i = 0; i < 8; i++)
#pragma unroll
        for (int j = 0; j < 8; j++) acc[i][j] = 0.f;

    for (int c0 = 0; c0 < Wn; c0 += 16) {
#pragma unroll
        for (int h = 0; h < 2; h++) {
            int q = tx * 2 + h;
            *(float4*)&Ws[ty][q * 4] = *(const float4*)&Wt[(c0 + ty) * Wn + q * 4];
            *(float4*)&Is[ty][q * 4] =
                *(const float4*)&inbase[(long)(b * Wn + c0 + ty) * Ln + l0 + q * 4];
        }
        __syncthreads();
        gemm_tile_compute(Ws, Is, tx, ty, acc);
        __syncthreads();
    }

    if (MODE == 0) {
        // spectral K-extension: 64 basis "channels", per-b coefficients
        for (int j0 = 0; j0 < J2; j0 += 16) {
#pragma unroll
            for (int h = 0; h < 2; h++) {
                int q = tx * 2 + h;
                *(float4*)&Ws[ty][q * 4] = *(const float4*)&g_spec[(b * J2 + j0 + ty) * Wn + q * 4];
                *(float4*)&Is[ty][q * 4] = *(const float4*)&g_basis[(long)(j0 + ty) * Ln + l0 + q * 4];
            }
            __syncthreads();
            gemm_tile_compute(Ws, Is, tx, ty, acc);
            __syncthreads();
        }
    }

    const int seg = l0 >> 11;   // l0 / 2048, constant over the 128-wide tile
#pragma unroll
    for (int i = 0; i < 8; i++) {
        const int o = tx * 8 + i;
        const float bi = bias[o];
        long base = (long)(b * Wn + o) * Ln + l0 + ty * 8;
        float outv[8];
        if (MODE == 1) {
            float gadd = g_g2v[(b * Wn + o) * SEGn + seg] + bi;
            float rc = g_rec[(b * Wn + o) * SEGn + seg];
            float4 f0 = *(const float4*)&g_fno[base];
            float4 f1 = *(const float4*)&g_fno[base + 4];
            float fn[8] = {f0.x, f0.y, f0.z, f0.w, f1.x, f1.y, f1.z, f1.w};
#pragma unroll
            for (int j = 0; j < 8; j++) {
                float g = 1.0f / (1.0f + expf(-(acc[i][j] + gadd)));
                outv[j] = fn[j] + g * rc;
            }
            *(float4*)&g_h[base] = make_float4(outv[0], outv[1], outv[2], outv[3]);
            *(float4*)&g_h[base + 4] = make_float4(outv[4], outv[5], outv[6], outv[7]);
        } else {
#pragma unroll
            for (int j = 0; j < 8; j++) outv[j] = gelu_exact(acc[i][j] + bi);
            *(float4*)&g_fno[base] = make_float4(outv[0], outv[1], outv[2], outv[3]);
            *(float4*)&g_fno[base + 4] = make_float4(outv[4], outv[5], outv[6], outv[7]);
        }
    }
}

// fc2: out[b,l] = sum_p g_fno[b,p,l]*w[p] + bias
__global__ void k_fc2(const float* __restrict__ w, const float* __restrict__ bias,
                      float* __restrict__ out) {
    int t = blockIdx.x * 256 + threadIdx.x;   // B*L
    int l = t & (Ln - 1);
    int b = t >> 13;
    float acc = bias[0];
    long base = (long)b * Wn * Ln + l;
#pragma unroll 4
    for (int p = 0; p < Wn; p++)
        acc += g_fno[base + (long)p * Ln] * w[p];
    out[t] = acc;
}

extern "C" void kernel_launch(void* const* d_in, const int* in_sizes, int n_in,
                              void* d_out, int out_size) {
    const float* x       = (const float*)d_in[0];
    const float* fc0_w   = (const float*)d_in[1];
    const float* fc0_b   = (const float*)d_in[2];
    const float* spec_wr = (const float*)d_in[3];
    const float* spec_wi = (const float*)d_in[4];
    const float* conv_w  = (const float*)d_in[5];
    const float* conv_b  = (const float*)d_in[6];
    const float* cheb_w  = (const float*)d_in[7];
    const float* gate_w  = (const float*)d_in[8];
    const float* gate_b  = (const float*)d_in[9];
    const float* fc1_w   = (const float*)d_in[10];
    const float* fc1_b   = (const float*)d_in[11];
    const float* fc2_w   = (const float*)d_in[12];
    const float* fc2_b   = (const float*)d_in[13];

    k_basis<<<(MODESn * Ln) / 256, 256>>>();
    k_wbar<<<NLn * SEGn * CMn, 128>>>(cheb_w);
    k_fc0<<<(Bn * Wn * Ln) / 256, 256>>>(x, fc0_w, fc0_b);

    for (int i = 0; i < NLn; i++) {
        k_init_mnmx<<<1, 32>>>();
        k_minmax<<<Bn * Wn * SEGn, 256>>>();
        k_cheb<<<Bn * Wn * SEGn, 256>>>(i);
        k_dft<<<dim3(16, KSPLIT), 256>>>();
        k_dft_reduce<<<(Bn * Wn * J2) / 256, 256>>>();
        k_modemix<<<dim3(16, Bn), 256>>>(spec_wr, spec_wi, i);
        k_g2<<<dim3(SEGn, Bn), 128>>>(gate_w, i);
        k_gemm<0><<<dim3(Ln / 128, Bn), 256>>>(conv_w + (long)i * Wn * Wn,
                                               conv_b + (long)i * Wn);
        k_gemm<1><<<dim3(Ln / 128, Bn), 256>>>(gate_w + (long)i * 2 * Wn * Wn,
                                               gate_b + (long)i * Wn);
    }
    k_gemm<2><<<dim3(Ln / 128, Bn), 256>>>(fc1_w, fc1_b);
    k_fc2<<<(Bn * Ln) / 256, 256>>>(fc2_w, fc2_b, (float*)d_out);
}